// round 15
// baseline (speedup 1.0000x reference)
#include <cuda_runtime.h>
#include <cuda_bf16.h>
#include <stdint.h>

// Problem constants
#define BB 8192   // batch
#define II 1024   // input size (K)
#define HH 512    // hidden per expert
#define EE 16     // experts
#define TT 4      // tasks
#define NN (EE*HH) // 8192 GEMM columns

// Scratch (device globals: allocation-free rule)
__device__ float g_gate_buf[BB * TT * EE];             // 2 MB softmax gates
__device__ __nv_bfloat16 g_x_hi[BB * II];              // 16 MB
__device__ __nv_bfloat16 g_x_lo[BB * II];              // 16 MB
__device__ __nv_bfloat16 g_w_hi[NN * II];              // 16 MB
__device__ __nv_bfloat16 g_w_lo[NN * II];              // 16 MB

// ---------------------------------------------------------------------------
// Split prepass: fp32 -> bf16 hi + bf16 lo (residual)
// ---------------------------------------------------------------------------
__global__ __launch_bounds__(256) void split_kernel(
    const float* __restrict__ src, __nv_bfloat16* __restrict__ hi,
    __nv_bfloat16* __restrict__ lo)
{
    const int i = blockIdx.x * 256 + threadIdx.x;
    float4 v = ((const float4*)src)[i];
    float f[4] = {v.x, v.y, v.z, v.w};
    __nv_bfloat162 h01, h23, l01, l23;
    __nv_bfloat16 h[4], l[4];
    #pragma unroll
    for (int k = 0; k < 4; ++k) {
        h[k] = __float2bfloat16(f[k]);
        l[k] = __float2bfloat16(f[k] - __bfloat162float(h[k]));
    }
    h01.x = h[0]; h01.y = h[1]; h23.x = h[2]; h23.y = h[3];
    l01.x = l[0]; l01.y = l[1]; l23.x = l[2]; l23.y = l[3];
    ((__nv_bfloat162*)hi)[2*i]   = h01;
    ((__nv_bfloat162*)hi)[2*i+1] = h23;
    ((__nv_bfloat162*)lo)[2*i]   = l01;
    ((__nv_bfloat162*)lo)[2*i+1] = l23;
}

// ---------------------------------------------------------------------------
// Gate kernel (verified): softmax gates + out init
// ---------------------------------------------------------------------------
__global__ __launch_bounds__(256) void gate_kernel(
    const float* __restrict__ x, const float* __restrict__ Wg,
    const float* __restrict__ bg, const float* __restrict__ bf,
    float* __restrict__ out)
{
    __shared__ float As[16][68];
    __shared__ float Bs[16][68];
    __shared__ float Ls[64][68];

    const int tid = threadIdx.x;
    const int tx = tid & 15, ty = tid >> 4;
    const int bm = blockIdx.x * 64;
    const int lrow = tid >> 2;
    const int lkq  = (tid & 3) << 2;

    float acc[4][4];
    #pragma unroll
    for (int i = 0; i < 4; ++i)
        #pragma unroll
        for (int j = 0; j < 4; ++j) acc[i][j] = 0.f;

    const float* pA = x  + (long)(bm + lrow) * II + lkq;
    const float* pB = Wg + (long)lrow * II + lkq;

    for (int k0 = 0; k0 < II; k0 += 16) {
        float4 va = *(const float4*)(pA + k0);
        float4 vb = *(const float4*)(pB + k0);
        As[lkq+0][lrow] = va.x; As[lkq+1][lrow] = va.y;
        As[lkq+2][lrow] = va.z; As[lkq+3][lrow] = va.w;
        Bs[lkq+0][lrow] = vb.x; Bs[lkq+1][lrow] = vb.y;
        Bs[lkq+2][lrow] = vb.z; Bs[lkq+3][lrow] = vb.w;
        __syncthreads();
        #pragma unroll
        for (int kk = 0; kk < 16; ++kk) {
            float a[4], b[4];
            #pragma unroll
            for (int i = 0; i < 4; ++i) a[i] = As[kk][ty*4+i];
            #pragma unroll
            for (int j = 0; j < 4; ++j) b[j] = Bs[kk][tx*4+j];
            #pragma unroll
            for (int i = 0; i < 4; ++i)
                #pragma unroll
                for (int j = 0; j < 4; ++j)
                    acc[i][j] = fmaf(a[i], b[j], acc[i][j]);
        }
        __syncthreads();
    }

    #pragma unroll
    for (int i = 0; i < 4; ++i)
        #pragma unroll
        for (int j = 0; j < 4; ++j)
            Ls[ty*4+i][tx*4+j] = acc[i][j] + bg[tx*4+j];
    __syncthreads();

    {
        const int row = tid >> 2, t = tid & 3;
        const float* L = &Ls[row][t*16];
        float m = L[0];
        #pragma unroll
        for (int e = 1; e < 16; ++e) m = fmaxf(m, L[e]);
        float ex[16], s = 0.f;
        #pragma unroll
        for (int e = 0; e < 16; ++e) { ex[e] = __expf(L[e] - m); s += ex[e]; }
        const float inv = 1.f / s;
        const int b = bm + row;
        #pragma unroll
        for (int e = 0; e < 16; ++e)
            g_gate_buf[b*64 + t*16 + e] = ex[e] * inv;
        out[t*BB + b] = bf[t];
    }
}

// ---------------------------------------------------------------------------
// Tensor-core expert kernel (mma.sync HMMA), bf16 3-split, K'=3072.
// BK=64, 48 chunks, 3-stage cp.async ring, R11 ordering (issue->commit->wait->
// sync->compute->sync), precomputed LDSM offsets (ks=2,3 = ks=0,1 ^ 64).
// Smem tile row = 128B (64 bf16); off = row*128 + ((c16 ^ (row&7))<<4).
// ---------------------------------------------------------------------------
#define NCH 48              // 3*1024/64
#define NSTAGE 3
#define STAGE_BYTES 32768   // 16KB A + 16KB B
#define OFF_B_IN_STAGE 16384

__device__ __forceinline__ uint32_t sw128(int row, int c16) {
    return (uint32_t)(row*128 + (((c16) ^ (row & 7)) << 4));
}

__global__ __launch_bounds__(256, 2) void expert_mma_kernel(
    const float* __restrict__ be, const float* __restrict__ Wf,
    float* __restrict__ out)
{
    extern __shared__ __align__(128) char smD[];  // 3 stages x 32KB
    __shared__ float wfS[4][128];
    __shared__ float beS[128];
    __shared__ float gS[128*4];
    __shared__ float red[128*4*4];                // [row][t][wn]

    const int tid  = threadIdx.x;
    const int wid  = tid >> 5;
    const int lane = tid & 31;
    const int wm = wid >> 2, wn = wid & 3;        // 2 x 4 warps
    const int g = lane >> 2, t = lane & 3;
    const int q = lane >> 3, ln7 = lane & 7;

    const int bn = blockIdx.x * 128;
    const int bm = blockIdx.y * 128;
    const int e  = bn >> 9;
    const int h0 = bn & (HH - 1);

    const uint32_t smu = (uint32_t)__cvta_generic_to_shared(smD);

    // cp.async mapping: thread -> row tid>>1, 64B half (tid&1), 4 x 16B each
    const int lr0 = tid >> 1, hf = tid & 1;
    uint32_t dstoff[4];
    #pragma unroll
    for (int i = 0; i < 4; ++i) dstoff[i] = sw128(lr0, hf*4 + i);

    // async copy: chunk c (BK=64) into given stage
    auto issue = [&](int stage, int c) {
        const int seg = c >> 4, k0 = (c & 15) << 6;
        const __nv_bfloat16* A = (seg == 2) ? g_x_lo : g_x_hi;
        const __nv_bfloat16* B = (seg == 1) ? g_w_lo : g_w_hi;
        const __nv_bfloat16* pa = A + (long)(bm + lr0) * II + k0 + hf*32;
        const __nv_bfloat16* pb = B + (long)(bn + lr0) * II + k0 + hf*32;
        const uint32_t ab = smu + stage*STAGE_BYTES;
        const uint32_t bb = ab + OFF_B_IN_STAGE;
        #pragma unroll
        for (int i = 0; i < 4; ++i) {
            asm volatile("cp.async.cg.shared.global [%0], [%1], 16;"
                         :: "r"(ab + dstoff[i]), "l"(pa + i*8));
            asm volatile("cp.async.cg.shared.global [%0], [%1], 16;"
                         :: "r"(bb + dstoff[i]), "l"(pb + i*8));
        }
    };

    // Prologue: fill stages 0,1 (distance-2 prefetch)
    issue(0, 0); asm volatile("cp.async.commit_group;");
    issue(1, 1); asm volatile("cp.async.commit_group;");

    // Epilogue operand fills (overlap with in-flight cp.async)
    for (int i = tid; i < 128; i += 256) beS[i] = be[e*HH + h0 + i];
    for (int i = tid; i < 512; i += 256) wfS[i>>7][i&127] = Wf[(i>>7)*HH + h0 + (i&127)];
    for (int i = tid; i < 512; i += 256)
        gS[i] = g_gate_buf[(bm + (i>>2))*64 + (i&3)*16 + e];

    // ldmatrix smem offsets for ks=0,1; ks=2,3 derived by ^64 (c16^4 => off^64)
    uint32_t offA[4][2], offB[4][2];
    #pragma unroll
    for (int mt = 0; mt < 4; ++mt)
        #pragma unroll
        for (int ks = 0; ks < 2; ++ks) {
            const int rowA = wm*64 + mt*16 + (q&1)*8 + ln7;
            offA[mt][ks] = sw128(rowA, 2*ks + (q>>1));
        }
    #pragma unroll
    for (int nt = 0; nt < 4; ++nt)
        #pragma unroll
        for (int ks = 0; ks < 2; ++ks) {
            const int rowB = wn*32 + nt*8 + ln7;
            offB[nt][ks] = sw128(rowB, 2*ks + (q&1));
        }

    float acc[4][4][4];
    #pragma unroll
    for (int a = 0; a < 4; ++a)
        #pragma unroll
        for (int b = 0; b < 4; ++b)
            #pragma unroll
            for (int k = 0; k < 4; ++k) acc[a][b][k] = 0.f;

    for (int c = 0; c < NCH; ++c) {
        // Stage (c+2)%3 was computed at iter c-1; end-of-iter sync protects it.
        if (c + 2 < NCH) issue((c + 2) % 3, c + 2);
        asm volatile("cp.async.commit_group;");      // uniform group counts
        asm volatile("cp.async.wait_group 2;");      // chunk c landed
        __syncthreads();

        const uint32_t xb = smu + (c % 3)*STAGE_BYTES;
        const uint32_t wb = xb + OFF_B_IN_STAGE;
        #pragma unroll
        for (int ks = 0; ks < 4; ++ks) {
            const uint32_t kx = (ks & 2) ? 64u : 0u;   // XOR-swizzle k-advance
            uint32_t bf_[4][2];
            #pragma unroll
            for (int nt = 0; nt < 4; ++nt)
                asm volatile("ldmatrix.sync.aligned.m8n8.x2.shared.b16 {%0,%1}, [%2];"
                    : "=r"(bf_[nt][0]), "=r"(bf_[nt][1])
                    : "r"(wb + (offB[nt][ks & 1] ^ kx)));
            #pragma unroll
            for (int mt = 0; mt < 4; ++mt) {
                uint32_t a0, a1, a2, a3;
                asm volatile("ldmatrix.sync.aligned.m8n8.x4.shared.b16 {%0,%1,%2,%3}, [%4];"
                    : "=r"(a0), "=r"(a1), "=r"(a2), "=r"(a3)
                    : "r"(xb + (offA[mt][ks & 1] ^ kx)));
                #pragma unroll
                for (int nt = 0; nt < 4; ++nt)
                    asm volatile(
                        "mma.sync.aligned.m16n8k16.row.col.f32.bf16.bf16.f32 "
                        "{%0,%1,%2,%3}, {%4,%5,%6,%7}, {%8,%9}, {%0,%1,%2,%3};"
                        : "+f"(acc[mt][nt][0]), "+f"(acc[mt][nt][1]),
                          "+f"(acc[mt][nt][2]), "+f"(acc[mt][nt][3])
                        : "r"(a0), "r"(a1), "r"(a2), "r"(a3),
                          "r"(bf_[nt][0]), "r"(bf_[nt][1]));
            }
        }
        __syncthreads();
    }

    // ---- Epilogue: relu(+be), dot Wf, reduce, gate, atomicAdd ----
    #pragma unroll
    for (int mt = 0; mt < 4; ++mt) {
        #pragma unroll
        for (int rs = 0; rs < 2; ++rs) {
            const int row_l = wm*64 + mt*16 + g + rs*8;
            float pt[4] = {0.f, 0.f, 0.f, 0.f};
            #pragma unroll
            for (int nt = 0; nt < 4; ++nt) {
                const int col0 = wn*32 + nt*8 + 2*t;
                float v0 = fmaxf(acc[mt][nt][rs*2+0] + beS[col0],     0.f);
                float v1 = fmaxf(acc[mt][nt][rs*2+1] + beS[col0 + 1], 0.f);
                #pragma unroll
                for (int tt = 0; tt < 4; ++tt)
                    pt[tt] += v0*wfS[tt][col0] + v1*wfS[tt][col0+1];
            }
            #pragma unroll
            for (int tt = 0; tt < 4; ++tt) {
                pt[tt] += __shfl_xor_sync(0xFFFFFFFFu, pt[tt], 1);
                pt[tt] += __shfl_xor_sync(0xFFFFFFFFu, pt[tt], 2);
            }
            if (t == 0) {
                #pragma unroll
                for (int tt = 0; tt < 4; ++tt)
                    red[(row_l*4 + tt)*4 + wn] = pt[tt];
            }
        }
    }
    __syncthreads();
    if (tid < 128) {
        const int row = tid;
        #pragma unroll
        for (int tt = 0; tt < 4; ++tt) {
            const float* r4 = &red[(row*4 + tt)*4];
            const float s = (r4[0] + r4[1]) + (r4[2] + r4[3]);
            atomicAdd(&out[tt*BB + bm + row], s * gS[row*4 + tt]);
        }
    }
}

// ---------------------------------------------------------------------------
// Launch. Inputs: x, We, be, Wg, bg, Wf, bf. Output f32 [T,B,1].
// ---------------------------------------------------------------------------
extern "C" void kernel_launch(void* const* d_in, const int* in_sizes, int n_in,
                              void* d_out, int out_size)
{
    const float* x  = (const float*)d_in[0];
    const float* We = (const float*)d_in[1];
    const float* be = (const float*)d_in[2];
    const float* Wg = (const float*)d_in[3];
    const float* bg = (const float*)d_in[4];
    const float* Wf = (const float*)d_in[5];
    const float* bf = (const float*)d_in[6];
    float* out = (float*)d_out;

    __nv_bfloat16 *xh, *xl, *wh, *wl;
    cudaGetSymbolAddress((void**)&xh, g_x_hi);
    cudaGetSymbolAddress((void**)&xl, g_x_lo);
    cudaGetSymbolAddress((void**)&wh, g_w_hi);
    cudaGetSymbolAddress((void**)&wl, g_w_lo);

    // 1) bf16 hi/lo split prepass
    split_kernel<<<(BB*II/4)/256, 256>>>(x,  xh, xl);
    split_kernel<<<(NN*II/4)/256, 256>>>(We, wh, wl);

    // 2) gates + softmax + out init
    gate_kernel<<<BB/64, 256>>>(x, Wg, bg, bf, out);

    // 3) tensor-core expert GEMM (bf16x3 via mma.sync, BK=64, 3-stage ring)
    cudaFuncSetAttribute(expert_mma_kernel,
                         cudaFuncAttributeMaxDynamicSharedMemorySize,
                         NSTAGE*STAGE_BYTES);
    dim3 grid(NN/128, BB/128);   // 64 x 64
    expert_mma_kernel<<<grid, 256, NSTAGE*STAGE_BYTES>>>(be, Wf, out);
}

// round 16
// speedup vs baseline: 1.2187x; 1.2187x over previous
#include <cuda_runtime.h>
#include <cuda_bf16.h>
#include <stdint.h>

// Problem constants
#define BB 8192   // batch
#define II 1024   // input size (K)
#define HH 512    // hidden per expert
#define EE 16     // experts
#define TT 4      // tasks
#define NN (EE*HH) // 8192 GEMM columns

// Scratch (device globals: allocation-free rule)
__device__ float g_gate_buf[BB * TT * EE];             // 2 MB softmax gates
__device__ __nv_bfloat16 g_x_hi[BB * II];              // 16 MB
__device__ __nv_bfloat16 g_x_lo[BB * II];              // 16 MB
__device__ __nv_bfloat16 g_w_hi[NN * II];              // 16 MB
__device__ __nv_bfloat16 g_w_lo[NN * II];              // 16 MB

// ---------------------------------------------------------------------------
// Split prepass: fp32 -> bf16 hi + bf16 lo (residual)
// ---------------------------------------------------------------------------
__global__ __launch_bounds__(256) void split_kernel(
    const float* __restrict__ src, __nv_bfloat16* __restrict__ hi,
    __nv_bfloat16* __restrict__ lo)
{
    const int i = blockIdx.x * 256 + threadIdx.x;
    float4 v = ((const float4*)src)[i];
    float f[4] = {v.x, v.y, v.z, v.w};
    __nv_bfloat162 h01, h23, l01, l23;
    __nv_bfloat16 h[4], l[4];
    #pragma unroll
    for (int k = 0; k < 4; ++k) {
        h[k] = __float2bfloat16(f[k]);
        l[k] = __float2bfloat16(f[k] - __bfloat162float(h[k]));
    }
    h01.x = h[0]; h01.y = h[1]; h23.x = h[2]; h23.y = h[3];
    l01.x = l[0]; l01.y = l[1]; l23.x = l[2]; l23.y = l[3];
    ((__nv_bfloat162*)hi)[2*i]   = h01;
    ((__nv_bfloat162*)hi)[2*i+1] = h23;
    ((__nv_bfloat162*)lo)[2*i]   = l01;
    ((__nv_bfloat162*)lo)[2*i+1] = l23;
}

// ---------------------------------------------------------------------------
// Gate kernel (verified): softmax gates + out init
// ---------------------------------------------------------------------------
__global__ __launch_bounds__(256) void gate_kernel(
    const float* __restrict__ x, const float* __restrict__ Wg,
    const float* __restrict__ bg, const float* __restrict__ bf,
    float* __restrict__ out)
{
    __shared__ float As[16][68];
    __shared__ float Bs[16][68];
    __shared__ float Ls[64][68];

    const int tid = threadIdx.x;
    const int tx = tid & 15, ty = tid >> 4;
    const int bm = blockIdx.x * 64;
    const int lrow = tid >> 2;
    const int lkq  = (tid & 3) << 2;

    float acc[4][4];
    #pragma unroll
    for (int i = 0; i < 4; ++i)
        #pragma unroll
        for (int j = 0; j < 4; ++j) acc[i][j] = 0.f;

    const float* pA = x  + (long)(bm + lrow) * II + lkq;
    const float* pB = Wg + (long)lrow * II + lkq;

    for (int k0 = 0; k0 < II; k0 += 16) {
        float4 va = *(const float4*)(pA + k0);
        float4 vb = *(const float4*)(pB + k0);
        As[lkq+0][lrow] = va.x; As[lkq+1][lrow] = va.y;
        As[lkq+2][lrow] = va.z; As[lkq+3][lrow] = va.w;
        Bs[lkq+0][lrow] = vb.x; Bs[lkq+1][lrow] = vb.y;
        Bs[lkq+2][lrow] = vb.z; Bs[lkq+3][lrow] = vb.w;
        __syncthreads();
        #pragma unroll
        for (int kk = 0; kk < 16; ++kk) {
            float a[4], b[4];
            #pragma unroll
            for (int i = 0; i < 4; ++i) a[i] = As[kk][ty*4+i];
            #pragma unroll
            for (int j = 0; j < 4; ++j) b[j] = Bs[kk][tx*4+j];
            #pragma unroll
            for (int i = 0; i < 4; ++i)
                #pragma unroll
                for (int j = 0; j < 4; ++j)
                    acc[i][j] = fmaf(a[i], b[j], acc[i][j]);
        }
        __syncthreads();
    }

    #pragma unroll
    for (int i = 0; i < 4; ++i)
        #pragma unroll
        for (int j = 0; j < 4; ++j)
            Ls[ty*4+i][tx*4+j] = acc[i][j] + bg[tx*4+j];
    __syncthreads();

    {
        const int row = tid >> 2, t = tid & 3;
        const float* L = &Ls[row][t*16];
        float m = L[0];
        #pragma unroll
        for (int e = 1; e < 16; ++e) m = fmaxf(m, L[e]);
        float ex[16], s = 0.f;
        #pragma unroll
        for (int e = 0; e < 16; ++e) { ex[e] = __expf(L[e] - m); s += ex[e]; }
        const float inv = 1.f / s;
        const int b = bm + row;
        #pragma unroll
        for (int e = 0; e < 16; ++e)
            g_gate_buf[b*64 + t*16 + e] = ex[e] * inv;
        out[t*BB + b] = bf[t];
    }
}

// ---------------------------------------------------------------------------
// Tensor-core expert kernel (mma.sync HMMA), bf16 3-split, K'=3072.
// R11 chunk machinery (BK=32, proven cp.async mapping, precomputed LDSM
// offsets) with PAIRED chunks: 4 stages x 16KB, one barrier interval covers
// 2 chunks (64 K-depth, 128 MMAs) -> 48 iterations, 2 syncs each (was 192).
// Swizzle: tile row = 64B (32 bf16); off = row*64 + ((k16^((row>>1)&3))<<4).
// ---------------------------------------------------------------------------
#define NCH 96              // 3*1024/32 chunks; 48 pairs
#define NPAIR 48
#define STAGE_BYTES 16384   // 8KB A + 8KB B per chunk-stage
#define OFF_B_IN_STAGE 8192

__device__ __forceinline__ uint32_t sw_off(int row, int k16) {
    return (uint32_t)(row*64 + (((k16) ^ ((row>>1)&3)) << 4));
}

__global__ __launch_bounds__(256, 2) void expert_mma_kernel(
    const float* __restrict__ be, const float* __restrict__ Wf,
    float* __restrict__ out)
{
    extern __shared__ __align__(128) char smD[];  // 4 stages x 16KB
    __shared__ float wfS[4][128];
    __shared__ float beS[128];
    __shared__ float gS[128*4];
    __shared__ float red[128*4*4];                // [row][t][wn]

    const int tid  = threadIdx.x;
    const int wid  = tid >> 5;
    const int lane = tid & 31;
    const int wm = wid >> 2, wn = wid & 3;        // 2 x 4 warps
    const int g = lane >> 2, t = lane & 3;
    const int q = lane >> 3, ln7 = lane & 7;

    const int bn = blockIdx.x * 128;
    const int bm = blockIdx.y * 128;
    const int e  = bn >> 9;
    const int h0 = bn & (HH - 1);

    const uint32_t smu = (uint32_t)__cvta_generic_to_shared(smD);

    // cp.async dst offsets (R11 mapping): rows (tid>>2), (tid>>2)+64, 16B col tid&3
    const int lr0 = tid >> 2, lk16 = tid & 3;
    const uint32_t d0 = sw_off(lr0, lk16);          // +4096 for row+64

    // async copy issue for chunk c into stage (c&3)  [R11 addressing, verbatim]
    auto issue = [&](int c) {
        const int kp = c * 32;                 // k' in [0,3072)
        const int seg = kp >> 10, k0 = kp & 1023;
        const __nv_bfloat16* A = (seg == 2) ? g_x_lo : g_x_hi;
        const __nv_bfloat16* B = (seg == 1) ? g_w_lo : g_w_hi;
        const long kelem = k0 + lk16*8;
        const char* sa0 = (const char*)(A + (long)(bm + lr0)     * II + kelem);
        const char* sa1 = (const char*)(A + (long)(bm + lr0 + 64)* II + kelem);
        const char* sb0 = (const char*)(B + (long)(bn + lr0)     * II + kelem);
        const char* sb1 = (const char*)(B + (long)(bn + lr0 + 64)* II + kelem);
        const uint32_t xb = smu + (c & 3)*STAGE_BYTES;
        const uint32_t wb = xb + OFF_B_IN_STAGE;
        asm volatile("cp.async.cg.shared.global [%0], [%1], 16;" :: "r"(xb + d0),        "l"(sa0));
        asm volatile("cp.async.cg.shared.global [%0], [%1], 16;" :: "r"(xb + d0 + 4096), "l"(sa1));
        asm volatile("cp.async.cg.shared.global [%0], [%1], 16;" :: "r"(wb + d0),        "l"(sb0));
        asm volatile("cp.async.cg.shared.global [%0], [%1], 16;" :: "r"(wb + d0 + 4096), "l"(sb1));
    };

    // Prologue: pair 0 (chunks 0,1 -> stages 0,1), one group
    issue(0); issue(1);
    asm volatile("cp.async.commit_group;");

    // Epilogue operand fills (overlap with in-flight cp.async)
    for (int i = tid; i < 128; i += 256) beS[i] = be[e*HH + h0 + i];
    for (int i = tid; i < 512; i += 256) wfS[i>>7][i&127] = Wf[(i>>7)*HH + h0 + (i&127)];
    for (int i = tid; i < 512; i += 256)
        gS[i] = g_gate_buf[(bm + (i>>2))*64 + (i&3)*16 + e];

    // ldmatrix smem offsets (per-lane constants, R11 verbatim)
    uint32_t offA[4][2], offB[4][2];
    #pragma unroll
    for (int mt = 0; mt < 4; ++mt)
        #pragma unroll
        for (int ks = 0; ks < 2; ++ks) {
            const int rowA = wm*64 + mt*16 + (q&1)*8 + ln7;
            offA[mt][ks] = sw_off(rowA, 2*ks + (q>>1));
        }
    #pragma unroll
    for (int nt = 0; nt < 4; ++nt)
        #pragma unroll
        for (int ks = 0; ks < 2; ++ks) {
            const int rowB = wn*32 + nt*8 + ln7;
            offB[nt][ks] = sw_off(rowB, 2*ks + (q&1));
        }

    float acc[4][4][4];
    #pragma unroll
    for (int a = 0; a < 4; ++a)
        #pragma unroll
        for (int b = 0; b < 4; ++b)
            #pragma unroll
            for (int k = 0; k < 4; ++k) acc[a][b][k] = 0.f;

    // compute one chunk resident in stage (c&3)  [R11 inner loop, verbatim]
    auto compute = [&](int c) {
        const uint32_t xb = smu + (c & 3)*STAGE_BYTES;
        const uint32_t wb = xb + OFF_B_IN_STAGE;
        #pragma unroll
        for (int ks = 0; ks < 2; ++ks) {
            uint32_t bf_[4][2];
            #pragma unroll
            for (int nt = 0; nt < 4; ++nt)
                asm volatile("ldmatrix.sync.aligned.m8n8.x2.shared.b16 {%0,%1}, [%2];"
                    : "=r"(bf_[nt][0]), "=r"(bf_[nt][1]) : "r"(wb + offB[nt][ks]));
            #pragma unroll
            for (int mt = 0; mt < 4; ++mt) {
                uint32_t a0, a1, a2, a3;
                asm volatile("ldmatrix.sync.aligned.m8n8.x4.shared.b16 {%0,%1,%2,%3}, [%4];"
                    : "=r"(a0), "=r"(a1), "=r"(a2), "=r"(a3) : "r"(xb + offA[mt][ks]));
                #pragma unroll
                for (int nt = 0; nt < 4; ++nt)
                    asm volatile(
                        "mma.sync.aligned.m16n8k16.row.col.f32.bf16.bf16.f32 "
                        "{%0,%1,%2,%3}, {%4,%5,%6,%7}, {%8,%9}, {%0,%1,%2,%3};"
                        : "+f"(acc[mt][nt][0]), "+f"(acc[mt][nt][1]),
                          "+f"(acc[mt][nt][2]), "+f"(acc[mt][nt][3])
                        : "r"(a0), "r"(a1), "r"(a2), "r"(a3),
                          "r"(bf_[nt][0]), "r"(bf_[nt][1]));
            }
        }
    };

    for (int cc = 0; cc < NPAIR; ++cc) {
        // Prefetch next pair into the opposite two stages (consumed at cc-1,
        // protected by the trailing sync of iteration cc-1).
        if (cc + 1 < NPAIR) { issue(2*cc + 2); issue(2*cc + 3); }
        asm volatile("cp.async.commit_group;");      // uniform group counts
        asm volatile("cp.async.wait_group 1;");      // pair cc landed
        __syncthreads();

        compute(2*cc);
        compute(2*cc + 1);
        __syncthreads();
    }

    // ---- Epilogue: relu(+be), dot Wf, reduce, gate, atomicAdd ----
    #pragma unroll
    for (int mt = 0; mt < 4; ++mt) {
        #pragma unroll
        for (int rs = 0; rs < 2; ++rs) {
            const int row_l = wm*64 + mt*16 + g + rs*8;
            float pt[4] = {0.f, 0.f, 0.f, 0.f};
            #pragma unroll
            for (int nt = 0; nt < 4; ++nt) {
                const int col0 = wn*32 + nt*8 + 2*t;
                float v0 = fmaxf(acc[mt][nt][rs*2+0] + beS[col0],     0.f);
                float v1 = fmaxf(acc[mt][nt][rs*2+1] + beS[col0 + 1], 0.f);
                #pragma unroll
                for (int tt = 0; tt < 4; ++tt)
                    pt[tt] += v0*wfS[tt][col0] + v1*wfS[tt][col0+1];
            }
            #pragma unroll
            for (int tt = 0; tt < 4; ++tt) {
                pt[tt] += __shfl_xor_sync(0xFFFFFFFFu, pt[tt], 1);
                pt[tt] += __shfl_xor_sync(0xFFFFFFFFu, pt[tt], 2);
            }
            if (t == 0) {
                #pragma unroll
                for (int tt = 0; tt < 4; ++tt)
                    red[(row_l*4 + tt)*4 + wn] = pt[tt];
            }
        }
    }
    __syncthreads();
    if (tid < 128) {
        const int row = tid;
        #pragma unroll
        for (int tt = 0; tt < 4; ++tt) {
            const float* r4 = &red[(row*4 + tt)*4];
            const float s = (r4[0] + r4[1]) + (r4[2] + r4[3]);
            atomicAdd(&out[tt*BB + bm + row], s * gS[row*4 + tt]);
        }
    }
}

// ---------------------------------------------------------------------------
// Launch. Inputs: x, We, be, Wg, bg, Wf, bf. Output f32 [T,B,1].
// ---------------------------------------------------------------------------
extern "C" void kernel_launch(void* const* d_in, const int* in_sizes, int n_in,
                              void* d_out, int out_size)
{
    const float* x  = (const float*)d_in[0];
    const float* We = (const float*)d_in[1];
    const float* be = (const float*)d_in[2];
    const float* Wg = (const float*)d_in[3];
    const float* bg = (const float*)d_in[4];
    const float* Wf = (const float*)d_in[5];
    const float* bf = (const float*)d_in[6];
    float* out = (float*)d_out;

    __nv_bfloat16 *xh, *xl, *wh, *wl;
    cudaGetSymbolAddress((void**)&xh, g_x_hi);
    cudaGetSymbolAddress((void**)&xl, g_x_lo);
    cudaGetSymbolAddress((void**)&wh, g_w_hi);
    cudaGetSymbolAddress((void**)&wl, g_w_lo);

    // 1) bf16 hi/lo split prepass
    split_kernel<<<(BB*II/4)/256, 256>>>(x,  xh, xl);
    split_kernel<<<(NN*II/4)/256, 256>>>(We, wh, wl);

    // 2) gates + softmax + out init
    gate_kernel<<<BB/64, 256>>>(x, Wg, bg, bf, out);

    // 3) tensor-core expert GEMM (bf16x3, paired-chunk 4-stage pipeline)
    cudaFuncSetAttribute(expert_mma_kernel,
                         cudaFuncAttributeMaxDynamicSharedMemorySize,
                         4*STAGE_BYTES);
    dim3 grid(NN/128, BB/128);   // 64 x 64
    expert_mma_kernel<<<grid, 256, 4*STAGE_BYTES>>>(be, Wf, out);
}

// round 17
// speedup vs baseline: 1.7577x; 1.4423x over previous
#include <cuda_runtime.h>
#include <cuda_fp16.h>
#include <stdint.h>

// Problem constants
#define BB 8192   // batch
#define II 1024   // input size (K)
#define HH 512    // hidden per expert
#define EE 16     // experts
#define TT 4      // tasks
#define NN (EE*HH) // 8192 GEMM columns

// Scratch (device globals: allocation-free rule)
__device__ float g_gate_buf[BB * TT * EE];   // 2 MB softmax gates
__device__ __half g_x_hi[BB * II];           // 16 MB  fp16(x)
__device__ __half g_x_lo[BB * II];           // 16 MB  fp16(x - fp16(x))
__device__ __half g_w[NN * II];              // 16 MB  fp16(We)

// ---------------------------------------------------------------------------
// Split prepass for x: fp32 -> fp16 hi + fp16 lo (residual)
// ---------------------------------------------------------------------------
__global__ __launch_bounds__(256) void split_x_kernel(
    const float* __restrict__ src, __half* __restrict__ hi,
    __half* __restrict__ lo)
{
    const int i = blockIdx.x * 256 + threadIdx.x;
    float4 v = ((const float4*)src)[i];
    float f[4] = {v.x, v.y, v.z, v.w};
    __half h[4], l[4];
    #pragma unroll
    for (int k = 0; k < 4; ++k) {
        h[k] = __float2half(f[k]);
        l[k] = __float2half(f[k] - __half2float(h[k]));
    }
    __half2 h01, h23, l01, l23;
    h01.x = h[0]; h01.y = h[1]; h23.x = h[2]; h23.y = h[3];
    l01.x = l[0]; l01.y = l[1]; l23.x = l[2]; l23.y = l[3];
    ((__half2*)hi)[2*i]   = h01;
    ((__half2*)hi)[2*i+1] = h23;
    ((__half2*)lo)[2*i]   = l01;
    ((__half2*)lo)[2*i+1] = l23;
}

// Convert prepass for We: fp32 -> fp16 (single term)
__global__ __launch_bounds__(256) void conv_w_kernel(
    const float* __restrict__ src, __half* __restrict__ dst)
{
    const int i = blockIdx.x * 256 + threadIdx.x;
    float4 v = ((const float4*)src)[i];
    __half2 h01, h23;
    h01.x = __float2half(v.x); h01.y = __float2half(v.y);
    h23.x = __float2half(v.z); h23.y = __float2half(v.w);
    ((__half2*)dst)[2*i]   = h01;
    ((__half2*)dst)[2*i+1] = h23;
}

// ---------------------------------------------------------------------------
// Gate kernel (verified): softmax gates + out init
// ---------------------------------------------------------------------------
__global__ __launch_bounds__(256) void gate_kernel(
    const float* __restrict__ x, const float* __restrict__ Wg,
    const float* __restrict__ bg, const float* __restrict__ bf,
    float* __restrict__ out)
{
    __shared__ float As[16][68];
    __shared__ float Bs[16][68];
    __shared__ float Ls[64][68];

    const int tid = threadIdx.x;
    const int tx = tid & 15, ty = tid >> 4;
    const int bm = blockIdx.x * 64;
    const int lrow = tid >> 2;
    const int lkq  = (tid & 3) << 2;

    float acc[4][4];
    #pragma unroll
    for (int i = 0; i < 4; ++i)
        #pragma unroll
        for (int j = 0; j < 4; ++j) acc[i][j] = 0.f;

    const float* pA = x  + (long)(bm + lrow) * II + lkq;
    const float* pB = Wg + (long)lrow * II + lkq;

    for (int k0 = 0; k0 < II; k0 += 16) {
        float4 va = *(const float4*)(pA + k0);
        float4 vb = *(const float4*)(pB + k0);
        As[lkq+0][lrow] = va.x; As[lkq+1][lrow] = va.y;
        As[lkq+2][lrow] = va.z; As[lkq+3][lrow] = va.w;
        Bs[lkq+0][lrow] = vb.x; Bs[lkq+1][lrow] = vb.y;
        Bs[lkq+2][lrow] = vb.z; Bs[lkq+3][lrow] = vb.w;
        __syncthreads();
        #pragma unroll
        for (int kk = 0; kk < 16; ++kk) {
            float a[4], b[4];
            #pragma unroll
            for (int i = 0; i < 4; ++i) a[i] = As[kk][ty*4+i];
            #pragma unroll
            for (int j = 0; j < 4; ++j) b[j] = Bs[kk][tx*4+j];
            #pragma unroll
            for (int i = 0; i < 4; ++i)
                #pragma unroll
                for (int j = 0; j < 4; ++j)
                    acc[i][j] = fmaf(a[i], b[j], acc[i][j]);
        }
        __syncthreads();
    }

    #pragma unroll
    for (int i = 0; i < 4; ++i)
        #pragma unroll
        for (int j = 0; j < 4; ++j)
            Ls[ty*4+i][tx*4+j] = acc[i][j] + bg[tx*4+j];
    __syncthreads();

    {
        const int row = tid >> 2, t = tid & 3;
        const float* L = &Ls[row][t*16];
        float m = L[0];
        #pragma unroll
        for (int e = 1; e < 16; ++e) m = fmaxf(m, L[e]);
        float ex[16], s = 0.f;
        #pragma unroll
        for (int e = 0; e < 16; ++e) { ex[e] = __expf(L[e] - m); s += ex[e]; }
        const float inv = 1.f / s;
        const int b = bm + row;
        #pragma unroll
        for (int e = 0; e < 16; ++e)
            g_gate_buf[b*64 + t*16 + e] = ex[e] * inv;
        out[t*BB + b] = bf[t];
    }
}

// ---------------------------------------------------------------------------
// Tensor-core expert kernel (mma.sync HMMA), fp16 2-split, K'=2048.
// R16 paired-chunk pipeline verbatim: BK=32 chunks, 4 stages x 16KB, one
// barrier interval covers 2 chunks -> 32 iterations, 2 syncs each.
// Swizzle: tile row = 64B (32 fp16); off = row*64 + ((k16^((row>>1)&3))<<4).
// ---------------------------------------------------------------------------
#define NCH 64              // 2*1024/32 chunks; 32 pairs
#define NPAIR 32
#define STAGE_BYTES 16384   // 8KB A + 8KB B per chunk-stage
#define OFF_B_IN_STAGE 8192

__device__ __forceinline__ uint32_t sw_off(int row, int k16) {
    return (uint32_t)(row*64 + (((k16) ^ ((row>>1)&3)) << 4));
}

__global__ __launch_bounds__(256, 2) void expert_mma_kernel(
    const float* __restrict__ be, const float* __restrict__ Wf,
    float* __restrict__ out)
{
    extern __shared__ __align__(128) char smD[];  // 4 stages x 16KB
    __shared__ float wfS[4][128];
    __shared__ float beS[128];
    __shared__ float gS[128*4];
    __shared__ float red[128*4*4];                // [row][t][wn]

    const int tid  = threadIdx.x;
    const int wid  = tid >> 5;
    const int lane = tid & 31;
    const int wm = wid >> 2, wn = wid & 3;        // 2 x 4 warps
    const int g = lane >> 2, t = lane & 3;
    const int q = lane >> 3, ln7 = lane & 7;

    const int bn = blockIdx.x * 128;
    const int bm = blockIdx.y * 128;
    const int e  = bn >> 9;
    const int h0 = bn & (HH - 1);

    const uint32_t smu = (uint32_t)__cvta_generic_to_shared(smD);

    // cp.async dst offsets (proven mapping): rows (tid>>2), (tid>>2)+64, col tid&3
    const int lr0 = tid >> 2, lk16 = tid & 3;
    const uint32_t d0 = sw_off(lr0, lk16);          // +4096 for row+64

    // async copy issue for chunk c into stage (c&3)
    // c in [0,64): seg 0 -> x_hi, seg 1 -> x_lo; B is always g_w.
    auto issue = [&](int c) {
        const int seg = c >> 5, k0 = (c & 31) << 5;
        const __half* A = seg ? g_x_lo : g_x_hi;
        const long kelem = k0 + lk16*8;
        const char* sa0 = (const char*)(A   + (long)(bm + lr0)     * II + kelem);
        const char* sa1 = (const char*)(A   + (long)(bm + lr0 + 64)* II + kelem);
        const char* sb0 = (const char*)(g_w + (long)(bn + lr0)     * II + kelem);
        const char* sb1 = (const char*)(g_w + (long)(bn + lr0 + 64)* II + kelem);
        const uint32_t xb = smu + (c & 3)*STAGE_BYTES;
        const uint32_t wb = xb + OFF_B_IN_STAGE;
        asm volatile("cp.async.cg.shared.global [%0], [%1], 16;" :: "r"(xb + d0),        "l"(sa0));
        asm volatile("cp.async.cg.shared.global [%0], [%1], 16;" :: "r"(xb + d0 + 4096), "l"(sa1));
        asm volatile("cp.async.cg.shared.global [%0], [%1], 16;" :: "r"(wb + d0),        "l"(sb0));
        asm volatile("cp.async.cg.shared.global [%0], [%1], 16;" :: "r"(wb + d0 + 4096), "l"(sb1));
    };

    // Prologue: pair 0 (chunks 0,1 -> stages 0,1), one group
    issue(0); issue(1);
    asm volatile("cp.async.commit_group;");

    // Epilogue operand fills (overlap with in-flight cp.async)
    for (int i = tid; i < 128; i += 256) beS[i] = be[e*HH + h0 + i];
    for (int i = tid; i < 512; i += 256) wfS[i>>7][i&127] = Wf[(i>>7)*HH + h0 + (i&127)];
    for (int i = tid; i < 512; i += 256)
        gS[i] = g_gate_buf[(bm + (i>>2))*64 + (i&3)*16 + e];

    // ldmatrix smem offsets (per-lane constants, verbatim)
    uint32_t offA[4][2], offB[4][2];
    #pragma unroll
    for (int mt = 0; mt < 4; ++mt)
        #pragma unroll
        for (int ks = 0; ks < 2; ++ks) {
            const int rowA = wm*64 + mt*16 + (q&1)*8 + ln7;
            offA[mt][ks] = sw_off(rowA, 2*ks + (q>>1));
        }
    #pragma unroll
    for (int nt = 0; nt < 4; ++nt)
        #pragma unroll
        for (int ks = 0; ks < 2; ++ks) {
            const int rowB = wn*32 + nt*8 + ln7;
            offB[nt][ks] = sw_off(rowB, 2*ks + (q&1));
        }

    float acc[4][4][4];
    #pragma unroll
    for (int a = 0; a < 4; ++a)
        #pragma unroll
        for (int b = 0; b < 4; ++b)
            #pragma unroll
            for (int k = 0; k < 4; ++k) acc[a][b][k] = 0.f;

    // compute one chunk resident in stage (c&3)  [fp16 MMA]
    auto compute = [&](int c) {
        const uint32_t xb = smu + (c & 3)*STAGE_BYTES;
        const uint32_t wb = xb + OFF_B_IN_STAGE;
        #pragma unroll
        for (int ks = 0; ks < 2; ++ks) {
            uint32_t bf_[4][2];
            #pragma unroll
            for (int nt = 0; nt < 4; ++nt)
                asm volatile("ldmatrix.sync.aligned.m8n8.x2.shared.b16 {%0,%1}, [%2];"
                    : "=r"(bf_[nt][0]), "=r"(bf_[nt][1]) : "r"(wb + offB[nt][ks]));
            #pragma unroll
            for (int mt = 0; mt < 4; ++mt) {
                uint32_t a0, a1, a2, a3;
                asm volatile("ldmatrix.sync.aligned.m8n8.x4.shared.b16 {%0,%1,%2,%3}, [%4];"
                    : "=r"(a0), "=r"(a1), "=r"(a2), "=r"(a3) : "r"(xb + offA[mt][ks]));
                #pragma unroll
                for (int nt = 0; nt < 4; ++nt)
                    asm volatile(
                        "mma.sync.aligned.m16n8k16.row.col.f32.f16.f16.f32 "
                        "{%0,%1,%2,%3}, {%4,%5,%6,%7}, {%8,%9}, {%0,%1,%2,%3};"
                        : "+f"(acc[mt][nt][0]), "+f"(acc[mt][nt][1]),
                          "+f"(acc[mt][nt][2]), "+f"(acc[mt][nt][3])
                        : "r"(a0), "r"(a1), "r"(a2), "r"(a3),
                          "r"(bf_[nt][0]), "r"(bf_[nt][1]));
            }
        }
    };

    for (int cc = 0; cc < NPAIR; ++cc) {
        // Prefetch next pair into the opposite two stages (consumed at cc-1,
        // protected by the trailing sync of iteration cc-1).
        if (cc + 1 < NPAIR) { issue(2*cc + 2); issue(2*cc + 3); }
        asm volatile("cp.async.commit_group;");      // uniform group counts
        asm volatile("cp.async.wait_group 1;");      // pair cc landed
        __syncthreads();

        compute(2*cc);
        compute(2*cc + 1);
        __syncthreads();
    }

    // ---- Epilogue: relu(+be), dot Wf, reduce, gate, atomicAdd ----
    #pragma unroll
    for (int mt = 0; mt < 4; ++mt) {
        #pragma unroll
        for (int rs = 0; rs < 2; ++rs) {
            const int row_l = wm*64 + mt*16 + g + rs*8;
            float pt[4] = {0.f, 0.f, 0.f, 0.f};
            #pragma unroll
            for (int nt = 0; nt < 4; ++nt) {
                const int col0 = wn*32 + nt*8 + 2*t;
                float v0 = fmaxf(acc[mt][nt][rs*2+0] + beS[col0],     0.f);
                float v1 = fmaxf(acc[mt][nt][rs*2+1] + beS[col0 + 1], 0.f);
                #pragma unroll
                for (int tt = 0; tt < 4; ++tt)
                    pt[tt] += v0*wfS[tt][col0] + v1*wfS[tt][col0+1];
            }
            #pragma unroll
            for (int tt = 0; tt < 4; ++tt) {
                pt[tt] += __shfl_xor_sync(0xFFFFFFFFu, pt[tt], 1);
                pt[tt] += __shfl_xor_sync(0xFFFFFFFFu, pt[tt], 2);
            }
            if (t == 0) {
                #pragma unroll
                for (int tt = 0; tt < 4; ++tt)
                    red[(row_l*4 + tt)*4 + wn] = pt[tt];
            }
        }
    }
    __syncthreads();
    if (tid < 128) {
        const int row = tid;
        #pragma unroll
        for (int tt = 0; tt < 4; ++tt) {
            const float* r4 = &red[(row*4 + tt)*4];
            const float s = (r4[0] + r4[1]) + (r4[2] + r4[3]);
            atomicAdd(&out[tt*BB + bm + row], s * gS[row*4 + tt]);
        }
    }
}

// ---------------------------------------------------------------------------
// Launch. Inputs: x, We, be, Wg, bg, Wf, bf. Output f32 [T,B,1].
// ---------------------------------------------------------------------------
extern "C" void kernel_launch(void* const* d_in, const int* in_sizes, int n_in,
                              void* d_out, int out_size)
{
    const float* x  = (const float*)d_in[0];
    const float* We = (const float*)d_in[1];
    const float* be = (const float*)d_in[2];
    const float* Wg = (const float*)d_in[3];
    const float* bg = (const float*)d_in[4];
    const float* Wf = (const float*)d_in[5];
    const float* bf = (const float*)d_in[6];
    float* out = (float*)d_out;

    __half *xh, *xl, *wh;
    cudaGetSymbolAddress((void**)&xh, g_x_hi);
    cudaGetSymbolAddress((void**)&xl, g_x_lo);
    cudaGetSymbolAddress((void**)&wh, g_w);

    // 1) fp16 prepass: x -> hi+lo split; We -> fp16
    split_x_kernel<<<(BB*II/4)/256, 256>>>(x, xh, xl);
    conv_w_kernel<<<(NN*II/4)/256, 256>>>(We, wh);

    // 2) gates + softmax + out init
    gate_kernel<<<BB/64, 256>>>(x, Wg, bg, bf, out);

    // 3) tensor-core expert GEMM (fp16 2-split, paired-chunk pipeline)
    cudaFuncSetAttribute(expert_mma_kernel,
                         cudaFuncAttributeMaxDynamicSharedMemorySize,
                         4*STAGE_BYTES);
    dim3 grid(NN/128, BB/128);   // 64 x 64
    expert_mma_kernel<<<grid, 256, 4*STAGE_BYTES>>>(be, Wf, out);
}